// round 6
// baseline (speedup 1.0000x reference)
#include <cuda_runtime.h>
#include <math.h>

#define BATCH 4
#define SEQ   2048
#define QDIM  1024
#define HEADS 16
#define DHEAD 64
#define MROWS (BATCH*SEQ)          // 8192
#define SCALE 0.125f
#define NKB   (SEQ/64)             // 32 key blocks

// tf32 scratch (device globals). A-side matrices stored k-interleaved:
// within each 8-col group, col k' lives at slot (k'>>2) + 2*(k'&3).
__device__ unsigned hid_tf[MROWS*QDIM];            // interleaved (A of qkv)
__device__ unsigned wq_tf[QDIM*QDIM];              // natural (B)
__device__ unsigned wk_tf[QDIM*QDIM];
__device__ unsigned wv_tf[QDIM*QDIM];
__device__ unsigned wo_tf[QDIM*QDIM];
__device__ unsigned g_q[BATCH*HEADS*SEQ*DHEAD];    // interleaved per 64-d row
__device__ unsigned g_k[BATCH*HEADS*SEQ*DHEAD];    // interleaved per 64-d row
__device__ unsigned g_v[BATCH*HEADS*SEQ*DHEAD];    // natural
__device__ unsigned g_att[MROWS*QDIM];             // interleaved (A of proj)

// ---------------------------------------------------------------------------
__device__ __forceinline__ unsigned f2tf(float x) {
    unsigned r;
    asm("cvt.rna.tf32.f32 %0, %1;" : "=r"(r) : "f"(x));
    return r;
}
__device__ __forceinline__ uint4 tf4(float4 v) {
    return make_uint4(f2tf(v.x), f2tf(v.y), f2tf(v.z), f2tf(v.w));
}
__device__ __forceinline__ void mma8(float c[4], const unsigned a[4], const unsigned b[2]) {
    asm volatile(
        "mma.sync.aligned.m16n8k8.row.col.f32.tf32.tf32.f32 "
        "{%0,%1,%2,%3}, {%4,%5,%6,%7}, {%8,%9}, {%0,%1,%2,%3};"
        : "+f"(c[0]), "+f"(c[1]), "+f"(c[2]), "+f"(c[3])
        : "r"(a[0]), "r"(a[1]), "r"(a[2]), "r"(a[3]), "r"(b[0]), "r"(b[1]));
}
__device__ __forceinline__ void cp16(unsigned* smem_dst, const void* gsrc) {
    unsigned s = (unsigned)__cvta_generic_to_shared(smem_dst);
    asm volatile("cp.async.cg.shared.global [%0], [%1], 16;" :: "r"(s), "l"(gsrc));
}
#define CP_COMMIT() asm volatile("cp.async.commit_group;")
#define CP_WAIT(N)  asm volatile("cp.async.wait_group %0;" :: "n"(N))

// ---------------------------------------------------------------------------
// One-shot tf32 conversion. hidden -> interleaved; Wq pre-scaled by SCALE.
// ---------------------------------------------------------------------------
#define HID4 (MROWS*QDIM/4)
#define W4   (QDIM*QDIM/4)
__global__ __launch_bounds__(256) void cvt_kernel(
    const float* __restrict__ hidden,
    const float* __restrict__ Wq, const float* __restrict__ Wk,
    const float* __restrict__ Wv, const float* __restrict__ Wo)
{
    int i = blockIdx.x * blockDim.x + threadIdx.x;
    if (i < HID4) {
        float4 v = reinterpret_cast<const float4*>(hidden)[i];
        int row = i >> 8, col = (i & 255) * 4;
        int s = col >> 3, bsel = (col >> 2) & 1;
        unsigned* d = &hid_tf[(size_t)row * QDIM + s * 8 + bsel];
        d[0] = f2tf(v.x); d[2] = f2tf(v.y); d[4] = f2tf(v.z); d[6] = f2tf(v.w);
    } else {
        int rel = i - HID4;
        int w = rel / W4, off = rel - w * W4;
        const float* src = (w == 0) ? Wq : (w == 1) ? Wk : (w == 2) ? Wv : Wo;
        unsigned*   dst  = (w == 0) ? wq_tf : (w == 1) ? wk_tf : (w == 2) ? wv_tf : wo_tf;
        float4 v = reinterpret_cast<const float4*>(src)[off];
        if (w == 0) { v.x *= SCALE; v.y *= SCALE; v.z *= SCALE; v.w *= SCALE; }
        reinterpret_cast<uint4*>(dst)[off] = tf4(v);
    }
}

// ---------------------------------------------------------------------------
// Dense GEMM: CTA 128x128x32, 8 warps (2m x 4n), warp tile 64x32.
// Double-buffered cp.async pipeline. A smem interleaved [128][56], B [32][136].
// ---------------------------------------------------------------------------
#define GBM 128
#define GBN 128
#define GBK 32
#define AST 56
#define BST 136
#define ABUF (GBM*AST)              // 7168
#define BBUF (GBK*BST)              // 4352
#define GEMM_SMEM ((2*ABUF + 2*BBUF) * 4)

__device__ __forceinline__ void gemm_issue(
    unsigned* As, unsigned* Bs,
    const unsigned* __restrict__ A, const unsigned* __restrict__ B,
    int bm, int bn, int k0, int tid)
{
    #pragma unroll
    for (int l = 0; l < 4; l++) {
        int lin = tid + l * 256;
        int row = lin >> 3, kg = lin & 7;
        cp16(&As[row * AST + kg * 4], &A[(size_t)(bm + row) * QDIM + k0 + kg * 4]);
    }
    #pragma unroll
    for (int l = 0; l < 4; l++) {
        int lin = tid + l * 256;
        int kk = lin >> 5, ng = lin & 31;
        cp16(&Bs[kk * BST + ng * 4], &B[(size_t)(k0 + kk) * QDIM + bn + ng * 4]);
    }
}

__device__ __forceinline__ void gemm_tile(
    const unsigned* As, const unsigned* Bs,
    int wm, int wn, int r, int kq, float acc[4][4][4])
{
    #pragma unroll
    for (int s = 0; s < 4; s++) {
        unsigned af[4][4];
        #pragma unroll
        for (int mi = 0; mi < 4; mi++) {
            int row = wm * 64 + mi * 16 + r;
            uint2 lo = *reinterpret_cast<const uint2*>(&As[row * AST + s * 8 + 2 * kq]);
            uint2 hi = *reinterpret_cast<const uint2*>(&As[(row + 8) * AST + s * 8 + 2 * kq]);
            af[mi][0] = lo.x; af[mi][2] = lo.y; af[mi][1] = hi.x; af[mi][3] = hi.y;
        }
        #pragma unroll
        for (int ni = 0; ni < 4; ni++) {
            int c = wn * 32 + ni * 8 + r;
            unsigned bf[2];
            bf[0] = Bs[(s * 8 + kq) * BST + c];
            bf[1] = Bs[(s * 8 + kq + 4) * BST + c];
            #pragma unroll
            for (int mi = 0; mi < 4; mi++) mma8(acc[mi][ni], af[mi], bf);
        }
    }
}

// Fused QKV projection -> g_q/g_k (interleaved), g_v (natural)
__global__ __launch_bounds__(256, 2) void qkv_kernel()
{
    const unsigned* B = (blockIdx.z == 0) ? wq_tf : ((blockIdx.z == 1) ? wk_tf : wv_tf);
    unsigned* dst     = (blockIdx.z == 0) ? g_q  : ((blockIdx.z == 1) ? g_k  : g_v);

    extern __shared__ unsigned gsm[];
    unsigned* As = gsm;                 // [2][ABUF]
    unsigned* Bs = gsm + 2 * ABUF;      // [2][BBUF]

    const int tid = threadIdx.x, lane = tid & 31, warp = tid >> 5;
    const int wm = warp >> 2, wn = warp & 3;
    const int r = lane >> 2, kq = lane & 3;
    const int bm = blockIdx.x * GBM;
    const int bn = blockIdx.y * GBN;

    float acc[4][4][4];
    #pragma unroll
    for (int mi = 0; mi < 4; mi++)
        #pragma unroll
        for (int ni = 0; ni < 4; ni++)
            #pragma unroll
            for (int c = 0; c < 4; c++) acc[mi][ni][c] = 0.f;

    gemm_issue(As, Bs, hid_tf, B, bm, bn, 0, tid);
    CP_COMMIT();

    for (int it = 0; it < QDIM / GBK; it++) {
        int cur = it & 1;
        if (it + 1 < QDIM / GBK) {
            gemm_issue(As + (cur ^ 1) * ABUF, Bs + (cur ^ 1) * BBUF,
                       hid_tf, B, bm, bn, (it + 1) * GBK, tid);
            CP_COMMIT();
            CP_WAIT(1);
        } else {
            CP_WAIT(0);
        }
        __syncthreads();
        gemm_tile(As + cur * ABUF, Bs + cur * BBUF, wm, wn, r, kq, acc);
        __syncthreads();
    }

    const int pslot = ((2 * kq) >> 2) + 2 * ((2 * kq) & 3);   // slot of col 2kq
    #pragma unroll
    for (int mi = 0; mi < 4; mi++) {
        #pragma unroll
        for (int ni = 0; ni < 4; ni++) {
            int m0 = bm + wm * 64 + mi * 16 + r;
            int d  = wn * 32 + ni * 8 + 2 * kq;
            int head = blockIdx.y * 2 + (d >> 6);
            int dd = d & 63;
            int b0 = m0 >> 11, t0 = m0 & 2047;
            int m1 = m0 + 8;
            int b1 = m1 >> 11, t1 = m1 & 2047;
            size_t base0 = ((size_t)(b0 * HEADS + head) * SEQ + t0) * DHEAD;
            size_t base1 = ((size_t)(b1 * HEADS + head) * SEQ + t1) * DHEAD;
            if (blockIdx.z == 2) {
                *reinterpret_cast<uint2*>(&dst[base0 + dd]) =
                    make_uint2(f2tf(acc[mi][ni][0]), f2tf(acc[mi][ni][1]));
                *reinterpret_cast<uint2*>(&dst[base1 + dd]) =
                    make_uint2(f2tf(acc[mi][ni][2]), f2tf(acc[mi][ni][3]));
            } else {
                size_t g0 = base0 + (dd >> 3) * 8 + pslot;
                size_t g1 = base1 + (dd >> 3) * 8 + pslot;
                dst[g0]     = f2tf(acc[mi][ni][0]);
                dst[g0 + 2] = f2tf(acc[mi][ni][1]);
                dst[g1]     = f2tf(acc[mi][ni][2]);
                dst[g1 + 2] = f2tf(acc[mi][ni][3]);
            }
        }
    }
}

// Output projection: out = g_att @ Wo + bo (f32 out)
__global__ __launch_bounds__(256, 2) void proj_kernel(
    const float* __restrict__ bo, float* __restrict__ C)
{
    extern __shared__ unsigned gsm[];
    unsigned* As = gsm;
    unsigned* Bs = gsm + 2 * ABUF;

    const int tid = threadIdx.x, lane = tid & 31, warp = tid >> 5;
    const int wm = warp >> 2, wn = warp & 3;
    const int r = lane >> 2, kq = lane & 3;
    const int bm = blockIdx.x * GBM;
    const int bn = blockIdx.y * GBN;

    float acc[4][4][4];
    #pragma unroll
    for (int mi = 0; mi < 4; mi++)
        #pragma unroll
        for (int ni = 0; ni < 4; ni++)
            #pragma unroll
            for (int c = 0; c < 4; c++) acc[mi][ni][c] = 0.f;

    gemm_issue(As, Bs, g_att, wo_tf, bm, bn, 0, tid);
    CP_COMMIT();

    for (int it = 0; it < QDIM / GBK; it++) {
        int cur = it & 1;
        if (it + 1 < QDIM / GBK) {
            gemm_issue(As + (cur ^ 1) * ABUF, Bs + (cur ^ 1) * BBUF,
                       g_att, wo_tf, bm, bn, (it + 1) * GBK, tid);
            CP_COMMIT();
            CP_WAIT(1);
        } else {
            CP_WAIT(0);
        }
        __syncthreads();
        gemm_tile(As + cur * ABUF, Bs + cur * BBUF, wm, wn, r, kq, acc);
        __syncthreads();
    }

    #pragma unroll
    for (int mi = 0; mi < 4; mi++) {
        #pragma unroll
        for (int ni = 0; ni < 4; ni++) {
            int m0 = bm + wm * 64 + mi * 16 + r;
            int d  = wn * 32 + ni * 8 + 2 * kq;
            float bx = bo[bn + d], by = bo[bn + d + 1];
            *reinterpret_cast<float2*>(&C[(size_t)m0 * QDIM + bn + d]) =
                make_float2(acc[mi][ni][0] + bx, acc[mi][ni][1] + by);
            *reinterpret_cast<float2*>(&C[(size_t)(m0 + 8) * QDIM + bn + d]) =
                make_float2(acc[mi][ni][2] + bx, acc[mi][ni][3] + by);
        }
    }
}

// ---------------------------------------------------------------------------
// Flash attention: CTA = 128 q rows x (b,h); 8 warps, warp = 16 rows x 64 cols.
// Q fragments hoisted to registers; Q-staging smem overlaid by P buffers.
// K/V/mask double-buffered via cp.async.
// ---------------------------------------------------------------------------
#define ATW 72
#define PST 72          // P row stride (>=64 cols; 72 fits exactly in overlay)
#define KVBUF (64*ATW)
// words: Qstage/P overlay 128*72=9216, K 2*4608, V 2*4608, mask 2*64
#define ATTN_SMEM ((128*ATW + 2*KVBUF + 2*KVBUF + 128) * 4)

__device__ __forceinline__ void attn_issue_kv(
    unsigned* Ksb, unsigned* Vsb, int* mskb,
    const unsigned* kgp, const unsigned* vgp, const int* mgp, int tid)
{
    #pragma unroll
    for (int l = 0; l < 4; l++) {
        int lin = tid + l * 256;
        int row = lin >> 4, kg = lin & 15;
        cp16(&Ksb[row * ATW + kg * 4], kgp + row * DHEAD + kg * 4);
        cp16(&Vsb[row * ATW + kg * 4], vgp + row * DHEAD + kg * 4);
    }
    if (tid < 16) cp16((unsigned*)&mskb[tid * 4], mgp + tid * 4);
}

__global__ __launch_bounds__(256, 2) void attn_kernel(const int* __restrict__ mask)
{
    extern __shared__ unsigned sm[];
    unsigned* Qstage = sm;                       // [128][72] (reused as P after)
    unsigned* Pw     = sm;                       // overlay: 8 x [16][PST]
    unsigned* Ks     = sm + 128 * ATW;           // [2][64*72]
    unsigned* Vs     = Ks + 2 * KVBUF;           // [2][64*72]
    int*      msk    = (int*)(Vs + 2 * KVBUF);   // [2][64]

    const int tid = threadIdx.x, lane = tid & 31, warp = tid >> 5;
    const int r = lane >> 2, kq = lane & 3;
    const int qb = blockIdx.x, h = blockIdx.y, b = blockIdx.z;
    const size_t bh = (size_t)(b * HEADS + h) * SEQ;
    const int row0 = warp * 16 + r;

    // issue Q + tile 0 (one group)
    const unsigned* qg = &g_q[(bh + qb * 128) * DHEAD];
    #pragma unroll
    for (int l = 0; l < 8; l++) {
        int lin = tid + l * 256;
        int row = lin >> 4, kg = lin & 15;
        cp16(&Qstage[row * ATW + kg * 4], qg + row * DHEAD + kg * 4);
    }
    attn_issue_kv(Ks, Vs, msk, &g_k[bh * DHEAD], &g_v[bh * DHEAD],
                  mask + b * SEQ, tid);
    CP_COMMIT();
    CP_WAIT(0);
    __syncthreads();

    // hoist Q fragments to registers
    unsigned qf[8][4];
    #pragma unroll
    for (int s = 0; s < 8; s++) {
        uint2 qlo = *reinterpret_cast<const uint2*>(&Qstage[row0 * ATW + s * 8 + 2 * kq]);
        uint2 qhi = *reinterpret_cast<const uint2*>(&Qstage[(row0 + 8) * ATW + s * 8 + 2 * kq]);
        qf[s][0] = qlo.x; qf[s][1] = qhi.x; qf[s][2] = qlo.y; qf[s][3] = qhi.y;
    }
    __syncthreads();   // all Q reads done before P overwrites the region

    float oacc[8][4];
    #pragma unroll
    for (int ni = 0; ni < 8; ni++)
        #pragma unroll
        for (int c = 0; c < 4; c++) oacc[ni][c] = 0.f;
    float m0 = -1e30f, m1 = -1e30f, l0 = 0.f, l1 = 0.f;

    unsigned* Pme = Pw + warp * 16 * PST;
    const int se0 = ((2 * kq) >> 2) + 2 * ((2 * kq) & 3);

    for (int kb = 0; kb < NKB; kb++) {
        int cur = kb & 1;
        if (kb + 1 < NKB) {
            attn_issue_kv(Ks + (cur ^ 1) * KVBUF, Vs + (cur ^ 1) * KVBUF,
                          msk + (cur ^ 1) * 64,
                          &g_k[(bh + (kb + 1) * 64) * DHEAD],
                          &g_v[(bh + (kb + 1) * 64) * DHEAD],
                          mask + b * SEQ + (kb + 1) * 64, tid);
            CP_COMMIT();
            CP_WAIT(1);
        } else {
            CP_WAIT(0);
        }
        __syncthreads();

        const unsigned* Kc = Ks + cur * KVBUF;
        const unsigned* Vc = Vs + cur * KVBUF;
        const int* mc = msk + cur * 64;

        // ---- S = Q K^T ----
        float sacc[8][4];
        #pragma unroll
        for (int ni = 0; ni < 8; ni++)
            #pragma unroll
            for (int c = 0; c < 4; c++) sacc[ni][c] = 0.f;

        #pragma unroll
        for (int s = 0; s < 8; s++) {
            #pragma unroll
            for (int ni = 0; ni < 8; ni++) {
                uint2 kf = *reinterpret_cast<const uint2*>(&Kc[(ni * 8 + r) * ATW + s * 8 + 2 * kq]);
                unsigned bf[2] = {kf.x, kf.y};
                mma8(sacc[ni], qf[s], bf);
            }
        }

        // ---- mask + register online softmax (rows r, r+8) ----
        float rx0 = -1e30f, rx1 = -1e30f;
        #pragma unroll
        for (int ni = 0; ni < 8; ni++) {
            int2 mi2 = *reinterpret_cast<const int2*>(&mc[ni * 8 + 2 * kq]);
            float mbx = mi2.x ? 0.f : -1e30f;
            float mby = mi2.y ? 0.f : -1e30f;
            sacc[ni][0] += mbx; sacc[ni][1] += mby;
            sacc[ni][2] += mbx; sacc[ni][3] += mby;
            rx0 = fmaxf(rx0, fmaxf(sacc[ni][0], sacc[ni][1]));
            rx1 = fmaxf(rx1, fmaxf(sacc[ni][2], sacc[ni][3]));
        }
        rx0 = fmaxf(rx0, __shfl_xor_sync(0xffffffffu, rx0, 1));
        rx0 = fmaxf(rx0, __shfl_xor_sync(0xffffffffu, rx0, 2));
        rx1 = fmaxf(rx1, __shfl_xor_sync(0xffffffffu, rx1, 1));
        rx1 = fmaxf(rx1, __shfl_xor_sync(0xffffffffu, rx1, 2));

        float mn0 = fmaxf(m0, rx0), mn1 = fmaxf(m1, rx1);
        float a0 = __expf(m0 - mn0), a1 = __expf(m1 - mn1);
        float rs0 = 0.f, rs1 = 0.f;
        #pragma unroll
        for (int ni = 0; ni < 8; ni++) {
            float p00 = __expf(sacc[ni][0] - mn0);
            float p01 = __expf(sacc[ni][1] - mn0);
            float p10 = __expf(sacc[ni][2] - mn1);
            float p11 = __expf(sacc[ni][3] - mn1);
            rs0 += p00 + p01; rs1 += p10 + p11;
            Pme[r * PST + ni * 8 + se0]           = f2tf(p00);
            Pme[r * PST + ni * 8 + se0 + 2]       = f2tf(p01);
            Pme[(r + 8) * PST + ni * 8 + se0]     = f2tf(p10);
            Pme[(r + 8) * PST + ni * 8 + se0 + 2] = f2tf(p11);
        }
        rs0 += __shfl_xor_sync(0xffffffffu, rs0, 1);
        rs0 += __shfl_xor_sync(0xffffffffu, rs0, 2);
        rs1 += __shfl_xor_sync(0xffffffffu, rs1, 1);
        rs1 += __shfl_xor_sync(0xffffffffu, rs1, 2);

        l0 = l0 * a0 + rs0; l1 = l1 * a1 + rs1;
        m0 = mn0; m1 = mn1;
        #pragma unroll
        for (int ni = 0; ni < 8; ni++) {
            oacc[ni][0] *= a0; oacc[ni][1] *= a0;
            oacc[ni][2] *= a1; oacc[ni][3] *= a1;
        }
        __syncwarp();

        // ---- O += P V ----
        #pragma unroll
        for (int s = 0; s < 8; s++) {
            uint2 plo = *reinterpret_cast<const uint2*>(&Pme[r * PST + s * 8 + 2 * kq]);
            uint2 phi = *reinterpret_cast<const uint2*>(&Pme[(r + 8) * PST + s * 8 + 2 * kq]);
            unsigned af[4] = {plo.x, phi.x, plo.y, phi.y};
            #pragma unroll
            for (int ni = 0; ni < 8; ni++) {
                unsigned bf[2];
                bf[0] = Vc[(s * 8 + kq) * ATW + ni * 8 + r];
                bf[1] = Vc[(s * 8 + kq + 4) * ATW + ni * 8 + r];
                mma8(oacc[ni], af, bf);
            }
        }
        __syncthreads();
    }

    // epilogue -> g_att (interleaved) [B,T,H*dh]
    float i0 = 1.f / l0, i1 = 1.f / l1;
    int t0 = qb * 128 + warp * 16 + r;
    size_t rb0 = ((size_t)(b * SEQ + t0) * QDIM) + h * DHEAD;
    size_t rb1 = ((size_t)(b * SEQ + t0 + 8) * QDIM) + h * DHEAD;
    #pragma unroll
    for (int ni = 0; ni < 8; ni++) {
        g_att[rb0 + ni * 8 + se0]     = f2tf(oacc[ni][0] * i0);
        g_att[rb0 + ni * 8 + se0 + 2] = f2tf(oacc[ni][1] * i0);
        g_att[rb1 + ni * 8 + se0]     = f2tf(oacc[ni][2] * i1);
        g_att[rb1 + ni * 8 + se0 + 2] = f2tf(oacc[ni][3] * i1);
    }
}

// ---------------------------------------------------------------------------
extern "C" void kernel_launch(void* const* d_in, const int* in_sizes, int n_in,
                              void* d_out, int out_size)
{
    const float* hidden = (const float*)d_in[0];
    const int*   amask  = (const int*)d_in[1];
    const float* Wq     = (const float*)d_in[2];
    const float* Wk     = (const float*)d_in[3];
    const float* Wv     = (const float*)d_in[4];
    const float* Wo     = (const float*)d_in[5];
    const float* bo     = (const float*)d_in[6];
    float* out          = (float*)d_out;

    cudaFuncSetAttribute(qkv_kernel,  cudaFuncAttributeMaxDynamicSharedMemorySize, GEMM_SMEM);
    cudaFuncSetAttribute(proj_kernel, cudaFuncAttributeMaxDynamicSharedMemorySize, GEMM_SMEM);
    cudaFuncSetAttribute(attn_kernel, cudaFuncAttributeMaxDynamicSharedMemorySize, ATTN_SMEM);

    cvt_kernel<<<(HID4 + 4 * W4 + 255) / 256, 256>>>(hidden, Wq, Wk, Wv, Wo);

    dim3 gq(MROWS / GBM, QDIM / GBN, 3);
    qkv_kernel<<<gq, 256, GEMM_SMEM>>>();

    dim3 ga(SEQ / 128, HEADS, BATCH);
    attn_kernel<<<ga, 256, ATTN_SMEM>>>(amask);

    dim3 gp(MROWS / GBM, QDIM / GBN);
    proj_kernel<<<gp, 256, GEMM_SMEM>>>(bo, out);
}

// round 11
// speedup vs baseline: 1.1869x; 1.1869x over previous
#include <cuda_runtime.h>
#include <math.h>

#define BATCH 4
#define SEQ   2048
#define QDIM  1024
#define HEADS 16
#define DHEAD 64
#define MROWS (BATCH*SEQ)          // 8192
#define SCALE 0.125f
#define NKB   (SEQ/64)

// tf32 scratch (device globals). Interleave: within each 8-col k-group,
// col k' lives at slot (k'>>2) + 2*(k'&3)  (pair (kq, kq+4) adjacent).
__device__ unsigned hid_tf[MROWS*QDIM];     // [M][K] k-interleaved (A of qkv)
__device__ unsigned wqt_tf[QDIM*QDIM];      // [N][K] transposed + k-interleaved
__device__ unsigned wkt_tf[QDIM*QDIM];
__device__ unsigned wvt_tf[QDIM*QDIM];
__device__ unsigned wot_tf[QDIM*QDIM];
__device__ unsigned g_q[BATCH*HEADS*SEQ*DHEAD];   // [B,H,T,dh] natural tf32 (pre-scaled)
__device__ unsigned g_k[BATCH*HEADS*SEQ*DHEAD];
__device__ unsigned g_v[BATCH*HEADS*SEQ*DHEAD];
__device__ unsigned g_att[MROWS*QDIM];            // [M][K] k-interleaved (A of proj)

// ---------------------------------------------------------------------------
__device__ __forceinline__ unsigned f2tf(float x) {
    unsigned r;
    asm("cvt.rna.tf32.f32 %0, %1;" : "=r"(r) : "f"(x));
    return r;
}
__device__ __forceinline__ void mma8(float c[4], const unsigned a[4], const unsigned b[2]) {
    asm volatile(
        "mma.sync.aligned.m16n8k8.row.col.f32.tf32.tf32.f32 "
        "{%0,%1,%2,%3}, {%4,%5,%6,%7}, {%8,%9}, {%0,%1,%2,%3};"
        : "+f"(c[0]), "+f"(c[1]), "+f"(c[2]), "+f"(c[3])
        : "r"(a[0]), "r"(a[1]), "r"(a[2]), "r"(a[3]), "r"(b[0]), "r"(b[1]));
}
__device__ __forceinline__ void cp16(void* smem_dst, const void* gsrc) {
    unsigned s = (unsigned)__cvta_generic_to_shared(smem_dst);
    asm volatile("cp.async.cg.shared.global [%0], [%1], 16;" :: "r"(s), "l"(gsrc));
}
#define CP_COMMIT() asm volatile("cp.async.commit_group;")
#define CP_WAIT(N)  asm volatile("cp.async.wait_group %0;" :: "n"(N))

// ---------------------------------------------------------------------------
// One-shot conversions
// ---------------------------------------------------------------------------
#define HID4 (MROWS*QDIM/4)
__global__ __launch_bounds__(256) void cvt_hid_kernel(const float* __restrict__ hidden)
{
    int i = blockIdx.x * blockDim.x + threadIdx.x;
    float4 v = reinterpret_cast<const float4*>(hidden)[i];
    int row = i >> 8, col = (i & 255) * 4;
    int s = col >> 3, bsel = (col >> 2) & 1;
    unsigned* d = &hid_tf[(size_t)row * QDIM + s * 8 + bsel];
    d[0] = f2tf(v.x); d[2] = f2tf(v.y); d[4] = f2tf(v.z); d[6] = f2tf(v.w);
}

// W[k][n] f32 -> Wt[n][k-interleaved] tf32. Wq pre-scaled by SCALE.
__global__ void wt_kernel(const float* __restrict__ Wq, const float* __restrict__ Wk,
                          const float* __restrict__ Wv, const float* __restrict__ Wo)
{
    const int w = blockIdx.z;
    const float* src = (w == 0) ? Wq : (w == 1) ? Wk : (w == 2) ? Wv : Wo;
    unsigned*   dst  = (w == 0) ? wqt_tf : (w == 1) ? wkt_tf : (w == 2) ? wvt_tf : wot_tf;

    __shared__ unsigned t[32][33];
    const int tx = threadIdx.x, ty = threadIdx.y;
    const int x  = blockIdx.x * 32 + tx;    // n
    const int y0 = blockIdx.y * 32;         // k base
    #pragma unroll
    for (int j = 0; j < 4; j++) {
        float v = src[(size_t)(y0 + ty + j * 8) * QDIM + x];
        if (w == 0) v *= SCALE;
        t[ty + j * 8][tx] = f2tf(v);
    }
    __syncthreads();
    // write row n, interleaved k
    const int kin = ((tx & 7) >> 2) + 2 * (tx & 3);   // slot within 8-group
    const int kcol = y0 + (tx >> 3) * 8 + kin;
    #pragma unroll
    for (int j = 0; j < 4; j++) {
        int n = blockIdx.x * 32 + ty + j * 8;
        dst[(size_t)n * QDIM + kcol] = t[tx][ty + j * 8];
    }
}

// ---------------------------------------------------------------------------
// Multistage GEMM: CTA 128x128, GBK=32, 3-stage cp.async, 8 warps (2m x 4n),
// warp tile 64x32. A and B both [128][STR=40] k-interleaved smem tiles.
// ---------------------------------------------------------------------------
#define GBK 32
#define NT  (QDIM/GBK)             // 32
#define STR 40
#define TILEW (128*STR)            // 5120 words
#define STAGEW (2*TILEW)
#define NSTAGE 3
#define GSMEM (NSTAGE*STAGEW*4)    // 122880 bytes

__device__ __forceinline__ void stage_issue(
    unsigned* As, unsigned* Bs,
    const unsigned* __restrict__ A, const unsigned* __restrict__ Bt,
    int bm, int bn, int k0, int tid)
{
    #pragma unroll
    for (int l = 0; l < 4; l++) {
        int lin = tid + l * 256;
        int row = lin >> 3, ch = lin & 7;       // 8 uint4 per 32-col row
        cp16(&As[row * STR + ch * 4], &A[(size_t)(bm + row) * QDIM + k0 + ch * 4]);
        cp16(&Bs[row * STR + ch * 4], &Bt[(size_t)(bn + row) * QDIM + k0 + ch * 4]);
    }
}

__device__ __forceinline__ void stage_compute(
    const unsigned* As, const unsigned* Bs,
    int wm, int wn, int r, int kq, float acc[4][4][4])
{
    #pragma unroll
    for (int s = 0; s < 4; s++) {
        unsigned af[4][4];
        #pragma unroll
        for (int mi = 0; mi < 4; mi++) {
            int row = wm * 64 + mi * 16 + r;
            uint2 lo = *reinterpret_cast<const uint2*>(&As[row * STR + s * 8 + 2 * kq]);
            uint2 hi = *reinterpret_cast<const uint2*>(&As[(row + 8) * STR + s * 8 + 2 * kq]);
            af[mi][0] = lo.x; af[mi][2] = lo.y; af[mi][1] = hi.x; af[mi][3] = hi.y;
        }
        #pragma unroll
        for (int ni = 0; ni < 4; ni++) {
            int c = wn * 32 + ni * 8 + r;
            uint2 bb = *reinterpret_cast<const uint2*>(&Bs[c * STR + s * 8 + 2 * kq]);
            unsigned bf[2] = {bb.x, bb.y};
            #pragma unroll
            for (int mi = 0; mi < 4; mi++) mma8(acc[mi][ni], af[mi], bf);
        }
    }
}

__device__ __forceinline__ void gemm_mainloop(
    const unsigned* __restrict__ A, const unsigned* __restrict__ Bt,
    int bm, int bn, unsigned* sm, int tid, int wm, int wn, int r, int kq,
    float acc[4][4][4])
{
    stage_issue(sm, sm + TILEW, A, Bt, bm, bn, 0, tid);
    CP_COMMIT();
    stage_issue(sm + STAGEW, sm + STAGEW + TILEW, A, Bt, bm, bn, GBK, tid);
    CP_COMMIT();

    for (int it = 0; it < NT; it++) {
        if (it + 1 < NT) { CP_WAIT(1); } else { CP_WAIT(0); }
        __syncthreads();
        if (it + 2 < NT) {
            unsigned* buf = sm + ((it + 2) % NSTAGE) * STAGEW;
            stage_issue(buf, buf + TILEW, A, Bt, bm, bn, (it + 2) * GBK, tid);
            CP_COMMIT();
        }
        const unsigned* cb = sm + (it % NSTAGE) * STAGEW;
        stage_compute(cb, cb + TILEW, wm, wn, r, kq, acc);
    }
}

// Fused QKV projection -> g_q/g_k/g_v natural [B,H,T,dh] tf32
__global__ __launch_bounds__(256) void qkv_kernel()
{
    const unsigned* Bt = (blockIdx.z == 0) ? wqt_tf : ((blockIdx.z == 1) ? wkt_tf : wvt_tf);
    unsigned* dst      = (blockIdx.z == 0) ? g_q   : ((blockIdx.z == 1) ? g_k   : g_v);

    extern __shared__ unsigned sm[];
    const int tid = threadIdx.x, lane = tid & 31, warp = tid >> 5;
    const int wm = warp >> 2, wn = warp & 3;
    const int r = lane >> 2, kq = lane & 3;
    const int bm = blockIdx.x * 128, bn = blockIdx.y * 128;

    float acc[4][4][4];
    #pragma unroll
    for (int mi = 0; mi < 4; mi++)
        #pragma unroll
        for (int ni = 0; ni < 4; ni++)
            #pragma unroll
            for (int c = 0; c < 4; c++) acc[mi][ni][c] = 0.f;

    gemm_mainloop(hid_tf, Bt, bm, bn, sm, tid, wm, wn, r, kq, acc);

    #pragma unroll
    for (int mi = 0; mi < 4; mi++) {
        #pragma unroll
        for (int ni = 0; ni < 4; ni++) {
            int m0 = bm + wm * 64 + mi * 16 + r;
            int d  = wn * 32 + ni * 8 + 2 * kq;
            int head = (bn + d) >> 6, dd = d & 63;
            int b0 = m0 >> 11, t0 = m0 & 2047;
            int m1 = m0 + 8;
            int b1 = m1 >> 11, t1 = m1 & 2047;
            *reinterpret_cast<uint2*>(
                &dst[(((size_t)(b0 * HEADS + head) * SEQ + t0) * DHEAD) + dd]) =
                make_uint2(f2tf(acc[mi][ni][0]), f2tf(acc[mi][ni][1]));
            *reinterpret_cast<uint2*>(
                &dst[(((size_t)(b1 * HEADS + head) * SEQ + t1) * DHEAD) + dd]) =
                make_uint2(f2tf(acc[mi][ni][2]), f2tf(acc[mi][ni][3]));
        }
    }
}

// Output projection: out = g_att @ Wo + bo (f32 out)
__global__ __launch_bounds__(256) void proj_kernel(
    const float* __restrict__ bo, float* __restrict__ C)
{
    extern __shared__ unsigned sm[];
    const int tid = threadIdx.x, lane = tid & 31, warp = tid >> 5;
    const int wm = warp >> 2, wn = warp & 3;
    const int r = lane >> 2, kq = lane & 3;
    const int bm = blockIdx.x * 128, bn = blockIdx.y * 128;

    float acc[4][4][4];
    #pragma unroll
    for (int mi = 0; mi < 4; mi++)
        #pragma unroll
        for (int ni = 0; ni < 4; ni++)
            #pragma unroll
            for (int c = 0; c < 4; c++) acc[mi][ni][c] = 0.f;

    gemm_mainloop(g_att, wot_tf, bm, bn, sm, tid, wm, wn, r, kq, acc);

    #pragma unroll
    for (int mi = 0; mi < 4; mi++) {
        #pragma unroll
        for (int ni = 0; ni < 4; ni++) {
            int m0 = bm + wm * 64 + mi * 16 + r;
            int d  = wn * 32 + ni * 8 + 2 * kq;
            float bx = bo[bn + d], by = bo[bn + d + 1];
            *reinterpret_cast<float2*>(&C[(size_t)m0 * QDIM + bn + d]) =
                make_float2(acc[mi][ni][0] + bx, acc[mi][ni][1] + by);
            *reinterpret_cast<float2*>(&C[(size_t)(m0 + 8) * QDIM + bn + d]) =
                make_float2(acc[mi][ni][2] + bx, acc[mi][ni][3] + by);
        }
    }
}

// ---------------------------------------------------------------------------
// Flash attention (R4-proven): CTA = 128 q rows x (b,h); 8 warps,
// warp = 16 rows x 64 cols; register online softmax; P in per-warp smem.
// Epilogue writes g_att k-interleaved (for proj's A side).
// ---------------------------------------------------------------------------
#define ATW 72
#define ATTN_SMEM ((128*ATW + 64*ATW + 64*ATW + 8*16*ATW) * 4 + 64 * 4)

__global__ __launch_bounds__(256, 2) void attn_kernel(const int* __restrict__ mask)
{
    extern __shared__ unsigned smu[];
    unsigned* Qs = smu;                       // [128][72] interleaved dh
    unsigned* Ks = Qs + 128 * ATW;            // [64][72] interleaved dh
    unsigned* Vs = Ks + 64 * ATW;             // [64][72] natural [key][d]
    unsigned* Pw = Vs + 64 * ATW;             // 8 x [16][72]
    float* mskf  = (float*)(Pw + 8 * 16 * ATW);   // [64]

    const int tid = threadIdx.x, lane = tid & 31, warp = tid >> 5;
    const int r = lane >> 2, kq = lane & 3;
    const int qb = blockIdx.x, h = blockIdx.y, b = blockIdx.z;
    const size_t bh = (size_t)(b * HEADS + h) * SEQ;

    const unsigned* qg = &g_q[(bh + qb * 128) * DHEAD];
    #pragma unroll
    for (int l = 0; l < 8; l++) {
        int lin = tid + l * 256;
        int row = lin >> 4, kg = lin & 15;
        uint4 v = *reinterpret_cast<const uint4*>(&qg[row * DHEAD + kg * 4]);
        unsigned* d = &Qs[row * ATW + (kg >> 1) * 8 + (kg & 1)];
        d[0] = v.x; d[2] = v.y; d[4] = v.z; d[6] = v.w;
    }

    float oacc[8][4];
    #pragma unroll
    for (int ni = 0; ni < 8; ni++)
        #pragma unroll
        for (int c = 0; c < 4; c++) oacc[ni][c] = 0.f;
    float m0 = -1e30f, m1 = -1e30f, l0 = 0.f, l1 = 0.f;

    unsigned* Pme = Pw + warp * 16 * ATW;
    const int row0 = warp * 16 + r;
    const int se0 = ((2 * kq) >> 2) + 2 * ((2 * kq) & 3);

    for (int kb = 0; kb < NKB; kb++) {
        __syncthreads();
        const unsigned* kgp = &g_k[(bh + kb * 64) * DHEAD];
        const unsigned* vgp = &g_v[(bh + kb * 64) * DHEAD];
        #pragma unroll
        for (int l = 0; l < 4; l++) {
            int lin = tid + l * 256;
            int row = lin >> 4, kg = lin & 15;
            uint4 kv = *reinterpret_cast<const uint4*>(&kgp[row * DHEAD + kg * 4]);
            unsigned* d = &Ks[row * ATW + (kg >> 1) * 8 + (kg & 1)];
            d[0] = kv.x; d[2] = kv.y; d[4] = kv.z; d[6] = kv.w;
            uint4 vv = *reinterpret_cast<const uint4*>(&vgp[row * DHEAD + kg * 4]);
            *reinterpret_cast<uint4*>(&Vs[row * ATW + kg * 4]) = vv;
        }
        if (tid < 64) mskf[tid] = (mask[b * SEQ + kb * 64 + tid] == 0) ? -1e30f : 0.f;
        __syncthreads();

        float sacc[8][4];
        #pragma unroll
        for (int ni = 0; ni < 8; ni++)
            #pragma unroll
            for (int c = 0; c < 4; c++) sacc[ni][c] = 0.f;

        #pragma unroll
        for (int s = 0; s < 8; s++) {
            uint2 qlo = *reinterpret_cast<const uint2*>(&Qs[row0 * ATW + s * 8 + 2 * kq]);
            uint2 qhi = *reinterpret_cast<const uint2*>(&Qs[(row0 + 8) * ATW + s * 8 + 2 * kq]);
            unsigned af[4] = {qlo.x, qhi.x, qlo.y, qhi.y};
            #pragma unroll
            for (int ni = 0; ni < 8; ni++) {
                uint2 kf = *reinterpret_cast<const uint2*>(&Ks[(ni * 8 + r) * ATW + s * 8 + 2 * kq]);
                unsigned bf[2] = {kf.x, kf.y};
                mma8(sacc[ni], af, bf);
            }
        }

        float rx0 = -1e30f, rx1 = -1e30f;
        #pragma unroll
        for (int ni = 0; ni < 8; ni++) {
            float2 mb = *reinterpret_cast<const float2*>(&mskf[ni * 8 + 2 * kq]);
            sacc[ni][0] += mb.x; sacc[ni][1] += mb.y;
            sacc[ni][2] += mb.x; sacc[ni][3] += mb.y;
            rx0 = fmaxf(rx0, fmaxf(sacc[ni][0], sacc[ni][1]));
            rx1 = fmaxf(rx1, fmaxf(sacc[ni][2], sacc[ni][3]));
        }
        rx0 = fmaxf(rx0, __shfl_xor_sync(0xffffffffu, rx0, 1));
        rx0 = fmaxf(rx0, __shfl_xor_sync(0xffffffffu, rx0, 2));
        rx1 = fmaxf(rx1, __shfl_xor_sync(0xffffffffu, rx1, 1));
        rx1 = fmaxf(rx1, __shfl_xor_sync(0xffffffffu, rx1, 2));

        float mn0 = fmaxf(m0, rx0), mn1 = fmaxf(m1, rx1);
        float a0 = __expf(m0 - mn0), a1 = __expf(m1 - mn1);
        float rs0 = 0.f, rs1 = 0.f;
        #pragma unroll
        for (int ni = 0; ni < 8; ni++) {
            float p00 = __expf(sacc[ni][0] - mn0);
            float p01 = __expf(sacc[ni][1] - mn0);
            float p10 = __expf(sacc[ni][2] - mn1);
            float p11 = __expf(sacc[ni][3] - mn1);
            rs0 += p00 + p01; rs1 += p10 + p11;
            Pme[r * ATW + ni * 8 + se0]           = f2tf(p00);
            Pme[r * ATW + ni * 8 + se0 + 2]       = f2tf(p01);
            Pme[(r + 8) * ATW + ni * 8 + se0]     = f2tf(p10);
            Pme[(r + 8) * ATW + ni * 8 + se0 + 2] = f2tf(p11);
        }
        rs0 += __shfl_xor_sync(0xffffffffu, rs0, 1);
        rs0 += __shfl_xor_sync(0xffffffffu, rs0, 2);
        rs1 += __shfl_xor_sync(0xffffffffu, rs1, 1);
        rs1 += __shfl_xor_sync(0xffffffffu, rs1, 2);

        l0 = l0 * a0 + rs0; l1 = l1 * a1 + rs1;
        m0 = mn0; m1 = mn1;
        #pragma unroll
        for (int ni = 0; ni < 8; ni++) {
            oacc[ni][0] *= a0; oacc[ni][1] *= a0;
            oacc[ni][2] *= a1; oacc[ni][3] *= a1;
        }
        __syncwarp();

        #pragma unroll
        for (int s = 0; s < 8; s++) {
            uint2 plo = *reinterpret_cast<const uint2*>(&Pme[r * ATW + s * 8 + 2 * kq]);
            uint2 phi = *reinterpret_cast<const uint2*>(&Pme[(r + 8) * ATW + s * 8 + 2 * kq]);
            unsigned af[4] = {plo.x, phi.x, plo.y, phi.y};
            #pragma unroll
            for (int ni = 0; ni < 8; ni++) {
                unsigned bf[2];
                bf[0] = Vs[(s * 8 + kq) * ATW + ni * 8 + r];
                bf[1] = Vs[(s * 8 + kq + 4) * ATW + ni * 8 + r];
                mma8(oacc[ni], af, bf);
            }
        }
    }

    // epilogue -> g_att k-interleaved [B,T,H*dh]
    float i0 = 1.f / l0, i1 = 1.f / l1;
    int t0 = qb * 128 + warp * 16 + r;
    size_t rb0 = ((size_t)(b * SEQ + t0) * QDIM) + h * DHEAD;
    size_t rb1 = ((size_t)(b * SEQ + t0 + 8) * QDIM) + h * DHEAD;
    #pragma unroll
    for (int ni = 0; ni < 8; ni++) {
        g_att[rb0 + ni * 8 + se0]     = f2tf(oacc[ni][0] * i0);
        g_att[rb0 + ni * 8 + se0 + 2] = f2tf(oacc[ni][1] * i0);
        g_att[rb1 + ni * 8 + se0]     = f2tf(oacc[ni][2] * i1);
        g_att[rb1 + ni * 8 + se0 + 2] = f2tf(oacc[ni][3] * i1);
    }
}

// ---------------------------------------------------------------------------
extern "C" void kernel_launch(void* const* d_in, const int* in_sizes, int n_in,
                              void* d_out, int out_size)
{
    const float* hidden = (const float*)d_in[0];
    const int*   amask  = (const int*)d_in[1];
    const float* Wq     = (const float*)d_in[2];
    const float* Wk     = (const float*)d_in[3];
    const float* Wv     = (const float*)d_in[4];
    const float* Wo     = (const float*)d_in[5];
    const float* bo     = (const float*)d_in[6];
    float* out          = (float*)d_out;

    cudaFuncSetAttribute(qkv_kernel,  cudaFuncAttributeMaxDynamicSharedMemorySize, GSMEM);
    cudaFuncSetAttribute(proj_kernel, cudaFuncAttributeMaxDynamicSharedMemorySize, GSMEM);
    cudaFuncSetAttribute(attn_kernel, cudaFuncAttributeMaxDynamicSharedMemorySize, ATTN_SMEM);

    cvt_hid_kernel<<<HID4 / 256, 256>>>(hidden);
    wt_kernel<<<dim3(QDIM / 32, QDIM / 32, 4), dim3(32, 8)>>>(Wq, Wk, Wv, Wo);

    dim3 gq(MROWS / 128, QDIM / 128, 3);
    qkv_kernel<<<gq, 256, GSMEM>>>();

    dim3 ga(SEQ / 128, HEADS, BATCH);
    attn_kernel<<<ga, 256, ATTN_SMEM>>>(amask);

    dim3 gp(MROWS / 128, QDIM / 128);
    proj_kernel<<<gp, 256, GSMEM>>>(bo, out);
}